// round 3
// baseline (speedup 1.0000x reference)
#include <cuda_runtime.h>

// out[0, z, r, c, ch] = in[0, z_idx[z], row_idx[r], col_idx[c], 0]
// in (1,128,128,128,32) f32; idx arrays 64 x int32; out (1,64,64,64,32) f32.
//
// One thread per OUTPUT VOXEL: one gathered scalar broadcast into 32 channels
// = 8 independent float4 streaming stores (128 contiguous bytes per thread,
// 4 KB contiguous per warp). z/r index loads are warp-uniform.

__global__ __launch_bounds__(256) void sd3d_kernel(
    const float* __restrict__ in,
    const int*   __restrict__ z_idx,
    const int*   __restrict__ row_idx,
    const int*   __restrict__ col_idx,
    float4*      __restrict__ out)
{
    int v = blockIdx.x * blockDim.x + threadIdx.x;   // voxel id, 0 .. 64^3-1
    int c = v & 63;
    int r = (v >> 6) & 63;
    int z = v >> 12;

    int zz = __ldg(z_idx + z);       // warp-uniform
    int rr = __ldg(row_idx + r);     // warp-uniform
    int cc = __ldg(col_idx + c);     // 32 distinct, one 128B line

    float val = __ldg(in + ((((long)zz * 128 + rr) * 128 + cc) << 5));

    float4 f = make_float4(val, val, val, val);
    float4* o = out + (size_t)v * 8;   // 32 floats = 8 float4 per voxel

#pragma unroll
    for (int i = 0; i < 8; i++)
        __stcs(o + i, f);              // streaming: write-once output
}

extern "C" void kernel_launch(void* const* d_in, const int* in_sizes, int n_in,
                              void* d_out, int out_size)
{
    const float* in      = (const float*)d_in[0];
    const int*   z_idx   = (const int*)d_in[1];
    const int*   row_idx = (const int*)d_in[2];
    const int*   col_idx = (const int*)d_in[3];
    float4* out = (float4*)d_out;

    const int n_vox = 64 * 64 * 64;        // 262144
    const int threads = 256;
    const int blocks = n_vox / threads;    // 1024
    sd3d_kernel<<<blocks, threads>>>(in, z_idx, row_idx, col_idx, out);
}

// round 4
// speedup vs baseline: 1.5364x; 1.5364x over previous
#include <cuda_runtime.h>

// out[0, z, r, c, ch] = in[0, z_idx[z], row_idx[r], col_idx[c], 0]
// in (1,128,128,128,32) f32; idx arrays 64 x int32; out (1,64,64,64,32) f32.
//
// R1 layout (1 float4 per work item: warp stores contiguous 512B, 8 lanes
// share one gather -> 4 coalesced gather lines per warp) x 8 independent
// iterations per thread (stride 262144 float4s) for MLP=8 latency hiding.

#define N_VEC4   (8388608 / 4)      // 2,097,152 float4 stores total
#define STRIDE   (N_VEC4 / 8)       // 262,144

__global__ __launch_bounds__(256) void sd3d_kernel(
    const float* __restrict__ in,
    const int*   __restrict__ z_idx,
    const int*   __restrict__ row_idx,
    const int*   __restrict__ col_idx,
    float4*      __restrict__ out)
{
    int t = blockIdx.x * blockDim.x + threadIdx.x;   // 0 .. 262,143

#pragma unroll
    for (int j = 0; j < 8; j++) {
        int f = t + j * STRIDE;      // float4 index, 0 .. 2,097,151
        int v = f >> 3;              // voxel id
        int c = v & 63;
        int r = (v >> 6) & 63;
        int z = v >> 12;

        int zz = __ldg(z_idx + z);
        int rr = __ldg(row_idx + r);
        int cc = __ldg(col_idx + c);

        float val = __ldg(in + ((((long)zz * 128 + rr) * 128 + cc) << 5));

        out[f] = make_float4(val, val, val, val);
    }
}

extern "C" void kernel_launch(void* const* d_in, const int* in_sizes, int n_in,
                              void* d_out, int out_size)
{
    const float* in      = (const float*)d_in[0];
    const int*   z_idx   = (const int*)d_in[1];
    const int*   row_idx = (const int*)d_in[2];
    const int*   col_idx = (const int*)d_in[3];
    float4* out = (float4*)d_out;

    const int threads = 256;
    const int blocks = STRIDE / threads;   // 1024
    sd3d_kernel<<<blocks, threads>>>(in, z_idx, row_idx, col_idx, out);
}